// round 1
// baseline (speedup 1.0000x reference)
#include <cuda_runtime.h>
#include <math.h>

constexpr int Bn = 4096;          // batch per view
constexpr int D  = 1024;          // feature dim
constexpr int NR = 8192;          // 2B rows
constexpr float INV_T = 1.0f / 0.07f;

constexpr int BM = 128, BN = 128, BK = 32;
constexpr int NTHREADS = 256;

// Scratch (device globals — no allocation allowed in kernel_launch)
__device__ float g_F[(size_t)NR * D];     // normalized features, 32 MB
__device__ float g_rowsum[NR];            // sum_j!=i exp(sim_ij)
__device__ float g_pos;                   // sum_i dot(f1n_i, f2n_i) / T

__device__ __forceinline__ float blockReduceSum(float v) {
    __shared__ float sh[32];
    int lane = threadIdx.x & 31;
    int wid  = threadIdx.x >> 5;
#pragma unroll
    for (int o = 16; o > 0; o >>= 1) v += __shfl_down_sync(0xffffffffu, v, o);
    if (lane == 0) sh[wid] = v;
    __syncthreads();
    int nw = blockDim.x >> 5;
    v = (threadIdx.x < nw) ? sh[lane] : 0.0f;
    if (wid == 0) {
#pragma unroll
        for (int o = 16; o > 0; o >>= 1) v += __shfl_down_sync(0xffffffffu, v, o);
    }
    return v;
}

__global__ void k_zero() {
    int t = blockIdx.x * blockDim.x + threadIdx.x;
    if (t < NR) g_rowsum[t] = 0.0f;
    if (t == 0) g_pos = 0.0f;
}

// One block per row: L2-normalize into g_F
__global__ void k_norm(const float* __restrict__ f1, const float* __restrict__ f2) {
    int row = blockIdx.x;
    const float* src = (row < Bn) ? (f1 + (size_t)row * D)
                                  : (f2 + (size_t)(row - Bn) * D);
    float ss = 0.0f;
    for (int d = threadIdx.x; d < D; d += NTHREADS) {
        float v = src[d];
        ss += v * v;
    }
    ss = blockReduceSum(ss);
    __shared__ float s_inv;
    if (threadIdx.x == 0) s_inv = 1.0f / fmaxf(sqrtf(ss), 1e-12f);
    __syncthreads();
    float inv = s_inv;
    float* dst = &g_F[(size_t)row * D];
    for (int d = threadIdx.x; d < D; d += NTHREADS) dst[d] = src[d] * inv;
}

// One block per i in [0,B): pos_i = dot(f1n_i, f2n_i) / T
__global__ void k_pos() {
    int i = blockIdx.x;
    const float* a = &g_F[(size_t)i * D];
    const float* b = &g_F[(size_t)(i + Bn) * D];
    float s = 0.0f;
    for (int d = threadIdx.x; d < D; d += NTHREADS) s += a[d] * b[d];
    s = blockReduceSum(s);
    if (threadIdx.x == 0) atomicAdd(&g_pos, s * INV_T);
}

// Tiled fp32 GEMM with fused exp + row-sum epilogue.
// gridDim.x = 64 M-tiles, gridDim.y = 4 N-splits (each covers 2048 cols).
__global__ void __launch_bounds__(NTHREADS, 2) k_gemm() {
    __shared__ float As[BK][BM + 4];
    __shared__ float Bs[BK][BN + 4];
    __shared__ float red[16][17];

    const int m0 = blockIdx.x * BM;
    const int n0 = blockIdx.y * (NR / 4);   // 2048-wide N range
    const int tx = threadIdx.x & 15;        // 0..15  (cols)
    const int ty = threadIdx.x >> 4;        // 0..15  (rows)
    const int t  = threadIdx.x;

    float rs[8];
#pragma unroll
    for (int r = 0; r < 8; r++) rs[r] = 0.0f;

    for (int nt = n0; nt < n0 + (NR / 4); nt += BN) {
        float c[8][8];
#pragma unroll
        for (int r = 0; r < 8; r++)
#pragma unroll
            for (int q = 0; q < 8; q++) c[r][q] = 0.0f;

        for (int k0 = 0; k0 < D; k0 += BK) {
            // cooperative load: 128 rows x 32 cols per tile, as float4
#pragma unroll
            for (int i = 0; i < 4; i++) {
                int idx = i * NTHREADS + t;      // 0..1023
                int m   = idx >> 3;              // 0..127
                int c4  = idx & 7;               // 0..7 -> k = c4*4
                float4 va = *(const float4*)&g_F[(size_t)(m0 + m) * D + k0 + c4 * 4];
                As[c4 * 4 + 0][m] = va.x;
                As[c4 * 4 + 1][m] = va.y;
                As[c4 * 4 + 2][m] = va.z;
                As[c4 * 4 + 3][m] = va.w;
                float4 vb = *(const float4*)&g_F[(size_t)(nt + m) * D + k0 + c4 * 4];
                Bs[c4 * 4 + 0][m] = vb.x;
                Bs[c4 * 4 + 1][m] = vb.y;
                Bs[c4 * 4 + 2][m] = vb.z;
                Bs[c4 * 4 + 3][m] = vb.w;
            }
            __syncthreads();

#pragma unroll
            for (int k = 0; k < BK; k++) {
                float a[8], b[8];
                *(float4*)(a)     = *(const float4*)&As[k][ty * 8];
                *(float4*)(a + 4) = *(const float4*)&As[k][ty * 8 + 4];
                *(float4*)(b)     = *(const float4*)&Bs[k][tx * 8];
                *(float4*)(b + 4) = *(const float4*)&Bs[k][tx * 8 + 4];
#pragma unroll
                for (int r = 0; r < 8; r++)
#pragma unroll
                    for (int q = 0; q < 8; q++)
                        c[r][q] = fmaf(a[r], b[q], c[r][q]);
            }
            __syncthreads();
        }

        // epilogue: exp + row-partial-sum, diagonal excluded
#pragma unroll
        for (int r = 0; r < 8; r++) {
            int i = m0 + ty * 8 + r;
#pragma unroll
            for (int q = 0; q < 8; q++) {
                int j = nt + tx * 8 + q;
                float e = (i == j) ? 0.0f : __expf(c[r][q] * INV_T);
                rs[r] += e;
            }
        }
    }

    // reduce the 16 tx-partials per row, one atomicAdd per row
#pragma unroll
    for (int r = 0; r < 8; r++) {
        red[ty][tx] = rs[r];
        __syncthreads();
        if (tx == 0) {
            float s = 0.0f;
#pragma unroll
            for (int q = 0; q < 16; q++) s += red[ty][q];
            atomicAdd(&g_rowsum[m0 + ty * 8 + r], s);
        }
        __syncthreads();
    }
}

__global__ void k_final(float* __restrict__ out) {
    float s = 0.0f;
    for (int i = threadIdx.x; i < NR; i += NTHREADS) s += logf(g_rowsum[i]);
    s = blockReduceSum(s);
    if (threadIdx.x == 0) {
        // loss = mean(lse) - mean(pos); mean(pos) over 2B = g_pos / B
        out[0] = s / (float)NR - g_pos / (float)Bn;
    }
}

extern "C" void kernel_launch(void* const* d_in, const int* in_sizes, int n_in,
                              void* d_out, int out_size) {
    const float* f1 = (const float*)d_in[0];
    const float* f2 = (const float*)d_in[1];
    float* out = (float*)d_out;

    k_zero<<<(NR + NTHREADS - 1) / NTHREADS, NTHREADS>>>();
    k_norm<<<NR, NTHREADS>>>(f1, f2);
    k_pos<<<Bn, NTHREADS>>>();
    dim3 grid(NR / BM, 4);
    k_gemm<<<grid, NTHREADS>>>();
    k_final<<<1, NTHREADS>>>(out);
}

// round 3
// speedup vs baseline: 14.1186x; 14.1186x over previous
#include <cuda_runtime.h>
#include <cuda_bf16.h>
#include <math.h>
#include <cstdint>

constexpr int Bn = 4096;
constexpr int D  = 1024;
constexpr int NR = 8192;
constexpr float INV_T = 1.0f / 0.07f;
constexpr float EXP2_SCALE = 1.4426950408889634f / 0.07f;   // log2(e)/T

constexpr int BM = 128, BN = 128, BK = 32;
constexpr int KITERS = D / BK;            // 32
constexpr int NSTAGE = 4;
constexpr int STRIDE = 40;                // halfs per smem row (80 B, conflict-free ldmatrix)
constexpr int TILE_BYTES  = 128 * STRIDE * 2;       // 10240
constexpr int STAGE_BYTES = 2 * TILE_BYTES;         // 20480
constexpr int SMEM_DYN = NSTAGE * STAGE_BYTES + 512 + 16;

__device__ __nv_bfloat16 g_Fb[(size_t)NR * D];   // normalized features, bf16
__device__ float g_rowsum[NR];
__device__ float g_pos;

// ---------------- helpers ----------------
__device__ __forceinline__ uint32_t smem_u32(const void* p) {
    uint32_t a;
    asm("{ .reg .u64 t; cvta.to.shared.u64 t, %1; cvt.u32.u64 %0, t; }" : "=r"(a) : "l"(p));
    return a;
}
__device__ __forceinline__ void cp16(uint32_t dst, const void* src) {
    asm volatile("cp.async.cg.shared.global [%0], [%1], 16;" :: "r"(dst), "l"(src) : "memory");
}
__device__ __forceinline__ void ldmx4(uint32_t* r, uint32_t addr) {
    asm volatile("ldmatrix.sync.aligned.m8n8.x4.shared.b16 {%0,%1,%2,%3}, [%4];"
                 : "=r"(r[0]), "=r"(r[1]), "=r"(r[2]), "=r"(r[3]) : "r"(addr));
}
__device__ __forceinline__ void mma_bf16(float* c, const uint32_t* a, uint32_t b0, uint32_t b1) {
    asm volatile("mma.sync.aligned.m16n8k16.row.col.f32.bf16.bf16.f32 "
                 "{%0,%1,%2,%3}, {%4,%5,%6,%7}, {%8,%9}, {%0,%1,%2,%3};"
                 : "+f"(c[0]), "+f"(c[1]), "+f"(c[2]), "+f"(c[3])
                 : "r"(a[0]), "r"(a[1]), "r"(a[2]), "r"(a[3]), "r"(b0), "r"(b1));
}
__device__ __forceinline__ float ex2(float x) {
    float r;
    asm("ex2.approx.ftz.f32 %0, %1;" : "=f"(r) : "f"(x));
    return r;
}
__device__ __forceinline__ float blockReduceSum(float v) {
    __shared__ float sh[32];
    int lane = threadIdx.x & 31, wid = threadIdx.x >> 5;
#pragma unroll
    for (int o = 16; o > 0; o >>= 1) v += __shfl_down_sync(0xffffffffu, v, o);
    if (lane == 0) sh[wid] = v;
    __syncthreads();
    int nw = blockDim.x >> 5;
    v = (threadIdx.x < nw) ? sh[lane] : 0.0f;
    if (wid == 0)
#pragma unroll
        for (int o = 16; o > 0; o >>= 1) v += __shfl_down_sync(0xffffffffu, v, o);
    return v;
}

// ---------------- small kernels ----------------
__global__ void k_zero() {
    int t = blockIdx.x * blockDim.x + threadIdx.x;
    if (t < NR) g_rowsum[t] = 0.0f;
    if (t == 0) g_pos = 0.0f;
}

__global__ void k_norm(const float* __restrict__ f1, const float* __restrict__ f2) {
    int row = blockIdx.x;
    const float* src = (row < Bn) ? (f1 + (size_t)row * D) : (f2 + (size_t)(row - Bn) * D);
    float ss = 0.0f;
    for (int d = threadIdx.x; d < D; d += 256) { float v = src[d]; ss += v * v; }
    ss = blockReduceSum(ss);
    __shared__ float s_inv;
    if (threadIdx.x == 0) s_inv = 1.0f / fmaxf(sqrtf(ss), 1e-12f);
    __syncthreads();
    float inv = s_inv;
    __nv_bfloat16* dst = &g_Fb[(size_t)row * D];
    for (int d = threadIdx.x; d < D; d += 256) dst[d] = __float2bfloat16(src[d] * inv);
}

__global__ void k_pos() {
    int i = blockIdx.x;
    const __nv_bfloat16* a = &g_Fb[(size_t)i * D];
    const __nv_bfloat16* b = &g_Fb[(size_t)(i + Bn) * D];
    float s = 0.0f;
    for (int d = threadIdx.x; d < D; d += 256)
        s += __bfloat162float(a[d]) * __bfloat162float(b[d]);
    s = blockReduceSum(s);
    if (threadIdx.x == 0) atomicAdd(&g_pos, s * INV_T);
}

__global__ void k_final(float* __restrict__ out) {
    float s = 0.0f;
    for (int i = threadIdx.x; i < NR; i += 256) s += logf(g_rowsum[i]);
    s = blockReduceSum(s);
    if (threadIdx.x == 0) out[0] = s / (float)NR - g_pos / (float)Bn;
}

// ---------------- main GEMM (upper triangle) + exp/rowsum ----------------
__global__ void __launch_bounds__(256, 2) k_gemm() {
    const int I = blockIdx.x, J = blockIdx.y;
    if (J < I) return;
    const bool diag = (I == J);
    const int m0 = I * BM, n0 = J * BN;

    extern __shared__ char smem_raw[];
    const uint32_t base = smem_u32(smem_raw);
    float* cs = (float*)(smem_raw + NSTAGE * STAGE_BYTES);

    const int tid = threadIdx.x, lane = tid & 31, wid = tid >> 5;
    const int wm = wid & 3, wn = wid >> 2;           // 4 x 2 warp grid

    if (tid < 128) cs[tid] = 0.0f;

    // cooperative stage loader: 1024 x 16B segments (A 512, B 512)
    auto load_stage = [&](int s, int k0) {
        const uint32_t st = base + s * STAGE_BYTES;
#pragma unroll
        for (int i = 0; i < 4; i++) {
            int seg = tid + i * 256;                 // 0..1023
            int r   = (seg >> 2) & 127;
            int c16 = seg & 3;
            bool isB = seg >= 512;
            uint32_t dst = st + (isB ? TILE_BYTES : 0) + r * (STRIDE * 2) + c16 * 16;
            int grow = (isB ? n0 : m0) + r;
            cp16(dst, &g_Fb[(size_t)grow * D + k0 + c16 * 8]);
        }
    };

    float c[2][8][4];
#pragma unroll
    for (int mi = 0; mi < 2; mi++)
#pragma unroll
        for (int f = 0; f < 8; f++)
#pragma unroll
            for (int q = 0; q < 4; q++) c[mi][f][q] = 0.0f;

    // prologue: fill 3 stages
#pragma unroll
    for (int s = 0; s < NSTAGE - 1; s++) {
        load_stage(s, s * BK);
        asm volatile("cp.async.commit_group;" ::: "memory");
    }

    for (int ki = 0; ki < KITERS; ki++) {
        asm volatile("cp.async.wait_group 2;" ::: "memory");
        __syncthreads();
        int pf = ki + NSTAGE - 1;
        if (pf < KITERS) load_stage(pf & (NSTAGE - 1), pf * BK);
        asm volatile("cp.async.commit_group;" ::: "memory");

        const uint32_t sA = base + (ki & (NSTAGE - 1)) * STAGE_BYTES;
        const uint32_t sB = sA + TILE_BYTES;
#pragma unroll
        for (int ks = 0; ks < 2; ks++) {
            uint32_t a[2][4];
            uint32_t a_addr = sA + (wm * 32 + (lane & 15)) * (STRIDE * 2)
                            + (ks * 16 + (lane >> 4) * 8) * 2;
            ldmx4(a[0], a_addr);
            ldmx4(a[1], a_addr + 16 * (STRIDE * 2));
#pragma unroll
            for (int nj = 0; nj < 4; nj++) {
                uint32_t b[4];
                uint32_t b_addr = sB + (wn * 64 + nj * 16 + (lane >> 4) * 8 + (lane & 7)) * (STRIDE * 2)
                                + (ks * 16 + ((lane >> 3) & 1) * 8) * 2;
                ldmx4(b, b_addr);
#pragma unroll
                for (int mi = 0; mi < 2; mi++) {
                    mma_bf16(c[mi][2 * nj],     a[mi], b[0], b[1]);
                    mma_bf16(c[mi][2 * nj + 1], a[mi], b[2], b[3]);
                }
            }
        }
    }
    asm volatile("cp.async.wait_group 0;" ::: "memory");

    // ---------------- epilogue ----------------
    float cacc[16];
#pragma unroll
    for (int q = 0; q < 16; q++) cacc[q] = 0.0f;

#pragma unroll
    for (int mi = 0; mi < 2; mi++) {
        const int r_lo = m0 + wm * 32 + mi * 16 + (lane >> 2);
        const int r_hi = r_lo + 8;
        float rs0 = 0.0f, rs1 = 0.0f;
#pragma unroll
        for (int f = 0; f < 8; f++) {
            const int j0 = n0 + wn * 64 + f * 8 + (lane & 3) * 2;
            float e0 = ex2(c[mi][f][0] * EXP2_SCALE);
            float e1 = ex2(c[mi][f][1] * EXP2_SCALE);
            float e2 = ex2(c[mi][f][2] * EXP2_SCALE);
            float e3 = ex2(c[mi][f][3] * EXP2_SCALE);
            if (diag) {
                if (r_lo == j0)     e0 = 0.0f;
                if (r_lo == j0 + 1) e1 = 0.0f;
                if (r_hi == j0)     e2 = 0.0f;
                if (r_hi == j0 + 1) e3 = 0.0f;
            }
            rs0 += e0 + e1;
            rs1 += e2 + e3;
            cacc[2 * f]     += e0 + e2;
            cacc[2 * f + 1] += e1 + e3;
        }
        rs0 += __shfl_xor_sync(0xffffffffu, rs0, 1);
        rs0 += __shfl_xor_sync(0xffffffffu, rs0, 2);
        rs1 += __shfl_xor_sync(0xffffffffu, rs1, 1);
        rs1 += __shfl_xor_sync(0xffffffffu, rs1, 2);
        if ((lane & 3) == 0) {
            atomicAdd(&g_rowsum[r_lo], rs0);
            atomicAdd(&g_rowsum[r_hi], rs1);
        }
    }

    if (!diag) {
        // column sums (symmetry): reduce over the 8 row-group lanes, then smem
#pragma unroll
        for (int q = 0; q < 16; q++) {
            float v = cacc[q];
            v += __shfl_xor_sync(0xffffffffu, v, 4);
            v += __shfl_xor_sync(0xffffffffu, v, 8);
            v += __shfl_xor_sync(0xffffffffu, v, 16);
            cacc[q] = v;
        }
        if (lane < 4) {
#pragma unroll
            for (int f = 0; f < 8; f++) {
#pragma unroll
                for (int p = 0; p < 2; p++) {
                    int jl = wn * 64 + f * 8 + lane * 2 + p;
                    atomicAdd(&cs[jl], cacc[2 * f + p]);
                }
            }
        }
        __syncthreads();
        if (tid < 128) atomicAdd(&g_rowsum[n0 + tid], cs[tid]);
    }
}

extern "C" void kernel_launch(void* const* d_in, const int* in_sizes, int n_in,
                              void* d_out, int out_size) {
    const float* f1 = (const float*)d_in[0];
    const float* f2 = (const float*)d_in[1];
    float* out = (float*)d_out;

    cudaFuncSetAttribute(k_gemm, cudaFuncAttributeMaxDynamicSharedMemorySize, SMEM_DYN);

    k_zero<<<(NR + 255) / 256, 256>>>();
    k_norm<<<NR, 256>>>(f1, f2);
    k_pos<<<Bn, 256>>>();
    dim3 grid(NR / BM, NR / BN);
    k_gemm<<<grid, 256, SMEM_DYN>>>();
    k_final<<<1, 256>>>(out);
}

// round 4
// speedup vs baseline: 15.7966x; 1.1189x over previous
#include <cuda_runtime.h>
#include <cuda_bf16.h>
#include <cuda_fp8.h>
#include <math.h>
#include <cstdint>

constexpr int Bn = 4096;
constexpr int D  = 1024;
constexpr int NR = 8192;
constexpr float INV_T = 1.0f / 0.07f;
// features stored as e4m3 of (f * 16); acc = 256 * sim
constexpr float FP8_SCALE = 16.0f;
constexpr float EXP2S = 1.4426950408889634f / (0.07f * 256.0f);

constexpr int BM = 128, BN = 128;
constexpr int BKB = 64;                   // K-bytes per stage row (64 fp8)
constexpr int KITERS = D / BKB;           // 16
constexpr int NSTAGE = 4;
constexpr int ROWB = 80;                  // bytes per smem row (64 data + 16 pad)
constexpr int TILE_BYTES  = 128 * ROWB;   // 10240
constexpr int STAGE_BYTES = 2 * TILE_BYTES;
constexpr int SMEM_DYN = NSTAGE * STAGE_BYTES + 512 + 16;
constexpr int NT = NR / BM;               // 64 tiles per dim
constexpr int NTRI = NT * (NT + 1) / 2;   // 2080 CTAs

__device__ uint8_t g_F8[(size_t)NR * D];  // normalized features * 16, e4m3
__device__ float g_rowsum[NR];
__device__ float g_pos;

// ---------------- helpers ----------------
__device__ __forceinline__ uint32_t smem_u32(const void* p) {
    uint32_t a;
    asm("{ .reg .u64 t; cvta.to.shared.u64 t, %1; cvt.u32.u64 %0, t; }" : "=r"(a) : "l"(p));
    return a;
}
__device__ __forceinline__ void cp16(uint32_t dst, const void* src) {
    asm volatile("cp.async.cg.shared.global [%0], [%1], 16;" :: "r"(dst), "l"(src) : "memory");
}
__device__ __forceinline__ void ldmx4(uint32_t* r, uint32_t addr) {
    asm volatile("ldmatrix.sync.aligned.m8n8.x4.shared.b16 {%0,%1,%2,%3}, [%4];"
                 : "=r"(r[0]), "=r"(r[1]), "=r"(r[2]), "=r"(r[3]) : "r"(addr));
}
__device__ __forceinline__ void mma_fp8(float* c, const uint32_t* a, uint32_t b0, uint32_t b1) {
    asm volatile("mma.sync.aligned.m16n8k32.row.col.f32.e4m3.e4m3.f32 "
                 "{%0,%1,%2,%3}, {%4,%5,%6,%7}, {%8,%9}, {%0,%1,%2,%3};"
                 : "+f"(c[0]), "+f"(c[1]), "+f"(c[2]), "+f"(c[3])
                 : "r"(a[0]), "r"(a[1]), "r"(a[2]), "r"(a[3]), "r"(b0), "r"(b1));
}
__device__ __forceinline__ float ex2(float x) {
    float r;
    asm("ex2.approx.ftz.f32 %0, %1;" : "=f"(r) : "f"(x));
    return r;
}
__device__ __forceinline__ float blockReduceSum(float v) {
    __shared__ float sh[32];
    int lane = threadIdx.x & 31, wid = threadIdx.x >> 5;
#pragma unroll
    for (int o = 16; o > 0; o >>= 1) v += __shfl_down_sync(0xffffffffu, v, o);
    if (lane == 0) sh[wid] = v;
    __syncthreads();
    int nw = blockDim.x >> 5;
    v = (threadIdx.x < nw) ? sh[lane] : 0.0f;
    if (wid == 0)
#pragma unroll
        for (int o = 16; o > 0; o >>= 1) v += __shfl_down_sync(0xffffffffu, v, o);
    return v;
}

// ---------------- small kernels ----------------
// normalize + quantize to e4m3(16*f); also zero accumulators
__global__ void k_norm(const float* __restrict__ f1, const float* __restrict__ f2) {
    int row = blockIdx.x;
    const float* src = (row < Bn) ? (f1 + (size_t)row * D) : (f2 + (size_t)(row - Bn) * D);
    float4 v = *(const float4*)&src[threadIdx.x * 4];
    float ss = v.x * v.x + v.y * v.y + v.z * v.z + v.w * v.w;
    ss = blockReduceSum(ss);
    __shared__ float s_inv;
    if (threadIdx.x == 0) {
        s_inv = FP8_SCALE / fmaxf(sqrtf(ss), 1e-12f);
        g_rowsum[row] = 0.0f;
        if (row == 0) g_pos = 0.0f;
    }
    __syncthreads();
    float inv = s_inv;
    __nv_fp8_e4m3 q0(v.x * inv), q1(v.y * inv), q2(v.z * inv), q3(v.w * inv);
    uchar4 packed = make_uchar4(*(uint8_t*)&q0, *(uint8_t*)&q1, *(uint8_t*)&q2, *(uint8_t*)&q3);
    *(uchar4*)&g_F8[(size_t)row * D + threadIdx.x * 4] = packed;
}

__global__ void k_pos() {
    int i = blockIdx.x;
    const uint8_t* a = &g_F8[(size_t)i * D];
    const uint8_t* b = &g_F8[(size_t)(i + Bn) * D];
    uchar4 pa = *(const uchar4*)&a[threadIdx.x * 4];
    uchar4 pb = *(const uchar4*)&b[threadIdx.x * 4];
    float s = 0.0f;
    s += float(*(__nv_fp8_e4m3*)&pa.x) * float(*(__nv_fp8_e4m3*)&pb.x);
    s += float(*(__nv_fp8_e4m3*)&pa.y) * float(*(__nv_fp8_e4m3*)&pb.y);
    s += float(*(__nv_fp8_e4m3*)&pa.z) * float(*(__nv_fp8_e4m3*)&pb.z);
    s += float(*(__nv_fp8_e4m3*)&pa.w) * float(*(__nv_fp8_e4m3*)&pb.w);
    s = blockReduceSum(s);
    if (threadIdx.x == 0) atomicAdd(&g_pos, s * (INV_T / 256.0f));
}

__global__ void k_final(float* __restrict__ out) {
    float s = 0.0f;
    for (int i = threadIdx.x; i < NR; i += 256) s += logf(g_rowsum[i]);
    s = blockReduceSum(s);
    if (threadIdx.x == 0) out[0] = s / (float)NR - g_pos / (float)Bn;
}

// ---------------- main GEMM (upper triangle) + exp/rowsum ----------------
__global__ void __launch_bounds__(256, 2) k_gemm() {
    // triangular decode: tile (I, J) with J >= I
    const int t = blockIdx.x;
    int I = (int)(64.5f - sqrtf(64.5f * 64.5f - 2.0f * (float)t));
    while (NT * I - I * (I - 1) / 2 > t) I--;
    while (NT * (I + 1) - (I + 1) * I / 2 <= t) I++;
    const int J = I + (t - (NT * I - I * (I - 1) / 2));
    const bool diag = (I == J);
    const int m0 = I * BM, n0 = J * BN;

    extern __shared__ char smem_raw[];
    const uint32_t base = smem_u32(smem_raw);
    float* cs = (float*)(smem_raw + NSTAGE * STAGE_BYTES);

    const int tid = threadIdx.x, lane = tid & 31, wid = tid >> 5;
    const int wm = wid & 3, wn = wid >> 2;           // 4 x 2 warp grid

    if (tid < 128) cs[tid] = 0.0f;

    // stage loader: 1024 x 16B segments (A 512, B 512); k0 in fp8 elements
    auto load_stage = [&](int s, int k0) {
        const uint32_t st = base + s * STAGE_BYTES;
#pragma unroll
        for (int i = 0; i < 4; i++) {
            int seg = tid + i * 256;
            int r   = (seg >> 2) & 127;
            int c16 = seg & 3;
            bool isB = seg >= 512;
            uint32_t dst = st + (isB ? TILE_BYTES : 0) + r * ROWB + c16 * 16;
            int grow = (isB ? n0 : m0) + r;
            cp16(dst, &g_F8[(size_t)grow * D + k0 + c16 * 16]);
        }
    };

    float c[2][8][4];
#pragma unroll
    for (int mi = 0; mi < 2; mi++)
#pragma unroll
        for (int f = 0; f < 8; f++)
#pragma unroll
            for (int q = 0; q < 4; q++) c[mi][f][q] = 0.0f;

#pragma unroll
    for (int s = 0; s < NSTAGE - 1; s++) {
        load_stage(s, s * BKB);
        asm volatile("cp.async.commit_group;" ::: "memory");
    }

    for (int ki = 0; ki < KITERS; ki++) {
        asm volatile("cp.async.wait_group 2;" ::: "memory");
        __syncthreads();
        int pf = ki + NSTAGE - 1;
        if (pf < KITERS) load_stage(pf & (NSTAGE - 1), pf * BKB);
        asm volatile("cp.async.commit_group;" ::: "memory");

        const uint32_t sA = base + (ki & (NSTAGE - 1)) * STAGE_BYTES;
        const uint32_t sB = sA + TILE_BYTES;
#pragma unroll
        for (int ks = 0; ks < 2; ks++) {           // two k32 slices per stage
            uint32_t a[2][4];
            uint32_t a_addr = sA + (wm * 32 + (lane & 15)) * ROWB
                            + ks * 32 + (lane >> 4) * 16;
            ldmx4(a[0], a_addr);
            ldmx4(a[1], a_addr + 16 * ROWB);
#pragma unroll
            for (int nj = 0; nj < 4; nj++) {
                uint32_t b[4];
                uint32_t b_addr = sB + (wn * 64 + nj * 16 + (lane >> 4) * 8 + (lane & 7)) * ROWB
                                + ks * 32 + ((lane >> 3) & 1) * 16;
                ldmx4(b, b_addr);
#pragma unroll
                for (int mi = 0; mi < 2; mi++) {
                    mma_fp8(c[mi][2 * nj],     a[mi], b[0], b[1]);
                    mma_fp8(c[mi][2 * nj + 1], a[mi], b[2], b[3]);
                }
            }
        }
    }
    asm volatile("cp.async.wait_group 0;" ::: "memory");

    // ---------------- epilogue ----------------
    float cacc[16];
#pragma unroll
    for (int q = 0; q < 16; q++) cacc[q] = 0.0f;

#pragma unroll
    for (int mi = 0; mi < 2; mi++) {
        const int r_lo = m0 + wm * 32 + mi * 16 + (lane >> 2);
        const int r_hi = r_lo + 8;
        float rs0 = 0.0f, rs1 = 0.0f;
#pragma unroll
        for (int f = 0; f < 8; f++) {
            const int j0 = n0 + wn * 64 + f * 8 + (lane & 3) * 2;
            float e0 = ex2(c[mi][f][0] * EXP2S);
            float e1 = ex2(c[mi][f][1] * EXP2S);
            float e2 = ex2(c[mi][f][2] * EXP2S);
            float e3 = ex2(c[mi][f][3] * EXP2S);
            if (diag) {
                if (r_lo == j0)     e0 = 0.0f;
                if (r_lo == j0 + 1) e1 = 0.0f;
                if (r_hi == j0)     e2 = 0.0f;
                if (r_hi == j0 + 1) e3 = 0.0f;
            }
            rs0 += e0 + e1;
            rs1 += e2 + e3;
            cacc[2 * f]     += e0 + e2;
            cacc[2 * f + 1] += e1 + e3;
        }
        rs0 += __shfl_xor_sync(0xffffffffu, rs0, 1);
        rs0 += __shfl_xor_sync(0xffffffffu, rs0, 2);
        rs1 += __shfl_xor_sync(0xffffffffu, rs1, 1);
        rs1 += __shfl_xor_sync(0xffffffffu, rs1, 2);
        if ((lane & 3) == 0) {
            atomicAdd(&g_rowsum[r_lo], rs0);
            atomicAdd(&g_rowsum[r_hi], rs1);
        }
    }

    if (!diag) {
#pragma unroll
        for (int q = 0; q < 16; q++) {
            float v = cacc[q];
            v += __shfl_xor_sync(0xffffffffu, v, 4);
            v += __shfl_xor_sync(0xffffffffu, v, 8);
            v += __shfl_xor_sync(0xffffffffu, v, 16);
            cacc[q] = v;
        }
        if (lane < 4) {
#pragma unroll
            for (int f = 0; f < 8; f++) {
#pragma unroll
                for (int p = 0; p < 2; p++) {
                    int jl = wn * 64 + f * 8 + lane * 2 + p;
                    atomicAdd(&cs[jl], cacc[2 * f + p]);
                }
            }
        }
        __syncthreads();
        if (tid < 128) atomicAdd(&g_rowsum[n0 + tid], cs[tid]);
    }
}

extern "C" void kernel_launch(void* const* d_in, const int* in_sizes, int n_in,
                              void* d_out, int out_size) {
    const float* f1 = (const float*)d_in[0];
    const float* f2 = (const float*)d_in[1];
    float* out = (float*)d_out;

    cudaFuncSetAttribute(k_gemm, cudaFuncAttributeMaxDynamicSharedMemorySize, SMEM_DYN);

    k_norm<<<NR, 256>>>(f1, f2);
    k_pos<<<Bn, 256>>>();
    k_gemm<<<NTRI, 256, SMEM_DYN>>>();
    k_final<<<1, 256>>>(out);
}

// round 5
// speedup vs baseline: 16.2480x; 1.0286x over previous
#include <cuda_runtime.h>
#include <cuda_bf16.h>
#include <cuda_fp8.h>
#include <math.h>
#include <cstdint>

constexpr int Bn = 4096;
constexpr int D  = 1024;
constexpr int NR = 8192;
constexpr float INV_T = 1.0f / 0.07f;
constexpr float FP8_SCALE = 16.0f;                         // features stored as e4m3(16*f)
constexpr float EXP2S = 1.4426950408889634f / (0.07f * 256.0f);

constexpr int BM = 128, BN = 128;
constexpr int BKB = 128;                  // fp8 K elems per stage (full 128-B row)
constexpr int KITERS = D / BKB;           // 8
constexpr int NSTAGE = 3;
constexpr int TILE_BYTES  = 128 * 128;    // 16384
constexpr int STAGE_BYTES = 2 * TILE_BYTES;
constexpr int SMEM_DYN = NSTAGE * STAGE_BYTES + 512 + 16;
constexpr int NT = NR / BM;               // 64
constexpr int NTRI = NT * (NT + 1) / 2;   // 2080

__device__ uint8_t g_F8[(size_t)NR * D];
__device__ float g_rowsum[NR];
__device__ float g_pos;

// ---------------- helpers ----------------
__device__ __forceinline__ uint32_t smem_u32(const void* p) {
    uint32_t a;
    asm("{ .reg .u64 t; cvta.to.shared.u64 t, %1; cvt.u32.u64 %0, t; }" : "=r"(a) : "l"(p));
    return a;
}
__device__ __forceinline__ void cp16(uint32_t dst, const void* src) {
    asm volatile("cp.async.cg.shared.global [%0], [%1], 16;" :: "r"(dst), "l"(src) : "memory");
}
__device__ __forceinline__ void ldmx4(uint32_t* r, uint32_t addr) {
    asm volatile("ldmatrix.sync.aligned.m8n8.x4.shared.b16 {%0,%1,%2,%3}, [%4];"
                 : "=r"(r[0]), "=r"(r[1]), "=r"(r[2]), "=r"(r[3]) : "r"(addr));
}
__device__ __forceinline__ void mma_fp8(float* c, const uint32_t* a, uint32_t b0, uint32_t b1) {
    asm volatile("mma.sync.aligned.m16n8k32.row.col.f32.e4m3.e4m3.f32 "
                 "{%0,%1,%2,%3}, {%4,%5,%6,%7}, {%8,%9}, {%0,%1,%2,%3};"
                 : "+f"(c[0]), "+f"(c[1]), "+f"(c[2]), "+f"(c[3])
                 : "r"(a[0]), "r"(a[1]), "r"(a[2]), "r"(a[3]), "r"(b0), "r"(b1));
}
__device__ __forceinline__ float ex2(float x) {
    float r;
    asm("ex2.approx.ftz.f32 %0, %1;" : "=f"(r) : "f"(x));
    return r;
}
__device__ __forceinline__ float warpReduceSum(float v) {
#pragma unroll
    for (int o = 16; o > 0; o >>= 1) v += __shfl_xor_sync(0xffffffffu, v, o);
    return v;
}
__device__ __forceinline__ float blockReduceSum(float v) {
    __shared__ float sh[32];
    int lane = threadIdx.x & 31, wid = threadIdx.x >> 5;
    v = warpReduceSum(v);
    if (lane == 0) sh[wid] = v;
    __syncthreads();
    int nw = blockDim.x >> 5;
    v = (threadIdx.x < nw) ? sh[lane] : 0.0f;
    if (wid == 0) v = warpReduceSum(v);
    return v;
}

// ---------------- small kernels ----------------
__global__ void k_norm(const float* __restrict__ f1, const float* __restrict__ f2) {
    int row = blockIdx.x;
    const float* src = (row < Bn) ? (f1 + (size_t)row * D) : (f2 + (size_t)(row - Bn) * D);
    float4 v = *(const float4*)&src[threadIdx.x * 4];
    float ss = v.x * v.x + v.y * v.y + v.z * v.z + v.w * v.w;
    ss = blockReduceSum(ss);
    __shared__ float s_inv;
    if (threadIdx.x == 0) {
        s_inv = FP8_SCALE / fmaxf(sqrtf(ss), 1e-12f);
        g_rowsum[row] = 0.0f;
        if (row == 0) g_pos = 0.0f;
    }
    __syncthreads();
    float inv = s_inv;
    __nv_fp8_e4m3 q0(v.x * inv), q1(v.y * inv), q2(v.z * inv), q3(v.w * inv);
    uchar4 packed = make_uchar4(*(uint8_t*)&q0, *(uint8_t*)&q1, *(uint8_t*)&q2, *(uint8_t*)&q3);
    *(uchar4*)&g_F8[(size_t)row * D + threadIdx.x * 4] = packed;
}

// warp per pair i: pos_i = dot(f8_i, f8_{i+Bn}) / (256 * T)
__global__ void k_pos() {
    int warp = (blockIdx.x * blockDim.x + threadIdx.x) >> 5;
    int lane = threadIdx.x & 31;
    if (warp >= Bn) return;
    const uint8_t* a = &g_F8[(size_t)warp * D];
    const uint8_t* b = &g_F8[(size_t)(warp + Bn) * D];
    float s = 0.0f;
#pragma unroll
    for (int j = 0; j < 8; j++) {
        int off = j * 128 + lane * 4;
        uchar4 pa = *(const uchar4*)&a[off];
        uchar4 pb = *(const uchar4*)&b[off];
        s += float(*(__nv_fp8_e4m3*)&pa.x) * float(*(__nv_fp8_e4m3*)&pb.x);
        s += float(*(__nv_fp8_e4m3*)&pa.y) * float(*(__nv_fp8_e4m3*)&pb.y);
        s += float(*(__nv_fp8_e4m3*)&pa.z) * float(*(__nv_fp8_e4m3*)&pb.z);
        s += float(*(__nv_fp8_e4m3*)&pa.w) * float(*(__nv_fp8_e4m3*)&pb.w);
    }
    s = warpReduceSum(s);
    if (lane == 0) atomicAdd(&g_pos, s * (INV_T / 256.0f));
}

__global__ void k_final(float* __restrict__ out) {
    float4 v0 = *(const float4*)&g_rowsum[threadIdx.x * 8];
    float4 v1 = *(const float4*)&g_rowsum[threadIdx.x * 8 + 4];
    float s = __logf(v0.x) + __logf(v0.y) + __logf(v0.z) + __logf(v0.w)
            + __logf(v1.x) + __logf(v1.y) + __logf(v1.z) + __logf(v1.w);
    s = blockReduceSum(s);
    if (threadIdx.x == 0) out[0] = s / (float)NR - g_pos / (float)Bn;
}

// ---------------- main GEMM (upper triangle) + exp/rowsum ----------------
__global__ void __launch_bounds__(256, 2) k_gemm() {
    const int t = blockIdx.x;
    int I = (int)(64.5f - sqrtf(64.5f * 64.5f - 2.0f * (float)t));
    while (NT * I - I * (I - 1) / 2 > t) I--;
    while (NT * (I + 1) - (I + 1) * I / 2 <= t) I++;
    const int J = I + (t - (NT * I - I * (I - 1) / 2));
    const bool diag = (I == J);
    const int m0 = I * BM, n0 = J * BN;

    extern __shared__ char smem_raw[];
    const uint32_t base = smem_u32(smem_raw);
    float* cs = (float*)(smem_raw + NSTAGE * STAGE_BYTES);

    const int tid = threadIdx.x, lane = tid & 31, wid = tid >> 5;
    const int wm = wid & 3, wn = wid >> 2;           // 4 x 2 warp grid

    if (tid < 128) cs[tid] = 0.0f;

    // stage loader: 2048 x 16B segments (A 1024, B 1024); swizzled 128B rows
    auto load_stage = [&](int s, int k0) {
        const uint32_t st = base + s * STAGE_BYTES;
#pragma unroll
        for (int i = 0; i < 8; i++) {
            int seg = tid + i * 256;                 // 0..2047
            int r   = seg >> 3;                      // 0..255
            int c   = seg & 7;                       // 16B chunk
            bool isB = r >= 128;
            int rl  = r & 127;
            uint32_t dst = st + (isB ? TILE_BYTES : 0) + rl * 128 + ((c ^ (rl & 7)) * 16);
            int grow = (isB ? n0 : m0) + rl;
            cp16(dst, &g_F8[(size_t)grow * D + k0 + c * 16]);
        }
    };

    float c[2][8][4];
#pragma unroll
    for (int mi = 0; mi < 2; mi++)
#pragma unroll
        for (int f = 0; f < 8; f++)
#pragma unroll
            for (int q = 0; q < 4; q++) c[mi][f][q] = 0.0f;

    load_stage(0, 0);
    asm volatile("cp.async.commit_group;" ::: "memory");
    load_stage(1, BKB);
    asm volatile("cp.async.commit_group;" ::: "memory");

    for (int ki = 0; ki < KITERS; ki++) {
        asm volatile("cp.async.wait_group 1;" ::: "memory");
        __syncthreads();
        if (ki + 2 < KITERS) load_stage((ki + 2) % NSTAGE, (ki + 2) * BKB);
        asm volatile("cp.async.commit_group;" ::: "memory");

        const uint32_t sA = base + (ki % NSTAGE) * STAGE_BYTES;
        const uint32_t sB = sA + TILE_BYTES;
#pragma unroll
        for (int ks = 0; ks < 4; ks++) {             // four k32 slices per stage
            uint32_t a[2][4];
#pragma unroll
            for (int mi = 0; mi < 2; mi++) {
                int rA = wm * 32 + mi * 16 + (lane & 15);
                int chA = ks * 2 + (lane >> 4);
                ldmx4(a[mi], sA + rA * 128 + ((chA ^ (rA & 7)) * 16));
            }
#pragma unroll
            for (int nj = 0; nj < 4; nj++) {
                uint32_t b[4];
                int rB = wn * 64 + nj * 16 + (lane >> 4) * 8 + (lane & 7);
                int chB = ks * 2 + ((lane >> 3) & 1);
                ldmx4(b, sB + rB * 128 + ((chB ^ (rB & 7)) * 16));
#pragma unroll
                for (int mi = 0; mi < 2; mi++) {
                    mma_fp8(c[mi][2 * nj],     a[mi], b[0], b[1]);
                    mma_fp8(c[mi][2 * nj + 1], a[mi], b[2], b[3]);
                }
            }
        }
    }
    asm volatile("cp.async.wait_group 0;" ::: "memory");

    // ---------------- epilogue ----------------
    float cacc[16];
#pragma unroll
    for (int q = 0; q < 16; q++) cacc[q] = 0.0f;

#pragma unroll
    for (int mi = 0; mi < 2; mi++) {
        const int r_lo = m0 + wm * 32 + mi * 16 + (lane >> 2);
        const int r_hi = r_lo + 8;
        float rs0 = 0.0f, rs1 = 0.0f;
#pragma unroll
        for (int f = 0; f < 8; f++) {
            const int j0 = n0 + wn * 64 + f * 8 + (lane & 3) * 2;
            float e0 = ex2(c[mi][f][0] * EXP2S);
            float e1 = ex2(c[mi][f][1] * EXP2S);
            float e2 = ex2(c[mi][f][2] * EXP2S);
            float e3 = ex2(c[mi][f][3] * EXP2S);
            if (diag) {
                if (r_lo == j0)     e0 = 0.0f;
                if (r_lo == j0 + 1) e1 = 0.0f;
                if (r_hi == j0)     e2 = 0.0f;
                if (r_hi == j0 + 1) e3 = 0.0f;
            }
            rs0 += e0 + e1;
            rs1 += e2 + e3;
            cacc[2 * f]     += e0 + e2;
            cacc[2 * f + 1] += e1 + e3;
        }
        rs0 += __shfl_xor_sync(0xffffffffu, rs0, 1);
        rs0 += __shfl_xor_sync(0xffffffffu, rs0, 2);
        rs1 += __shfl_xor_sync(0xffffffffu, rs1, 1);
        rs1 += __shfl_xor_sync(0xffffffffu, rs1, 2);
        if ((lane & 3) == 0) {
            atomicAdd(&g_rowsum[r_lo], rs0);
            atomicAdd(&g_rowsum[r_hi], rs1);
        }
    }

    if (!diag) {
#pragma unroll
        for (int q = 0; q < 16; q++) {
            float v = cacc[q];
            v += __shfl_xor_sync(0xffffffffu, v, 4);
            v += __shfl_xor_sync(0xffffffffu, v, 8);
            v += __shfl_xor_sync(0xffffffffu, v, 16);
            cacc[q] = v;
        }
        if (lane < 4) {
#pragma unroll
            for (int f = 0; f < 8; f++) {
#pragma unroll
                for (int p = 0; p < 2; p++) {
                    int jl = wn * 64 + f * 8 + lane * 2 + p;
                    atomicAdd(&cs[jl], cacc[2 * f + p]);
                }
            }
        }
        __syncthreads();
        if (tid < 128) atomicAdd(&g_rowsum[n0 + tid], cs[tid]);
    }
}

extern "C" void kernel_launch(void* const* d_in, const int* in_sizes, int n_in,
                              void* d_out, int out_size) {
    const float* f1 = (const float*)d_in[0];
    const float* f2 = (const float*)d_in[1];
    float* out = (float*)d_out;

    cudaFuncSetAttribute(k_gemm, cudaFuncAttributeMaxDynamicSharedMemorySize, SMEM_DYN);

    k_norm<<<NR, 256>>>(f1, f2);
    k_pos<<<(Bn * 32 + 255) / 256, 256>>>();
    k_gemm<<<NTRI, 256, SMEM_DYN>>>();
    k_final<<<1, 1024>>>(out);
}